// round 1
// baseline (speedup 1.0000x reference)
#include <cuda_runtime.h>
#include <math.h>

#define HID  2048
#define NSEQ 2048
#define NH   16
#define HD   128
#define TOPK 256

// ---------------- scratch (device globals; no allocation) ----------------
__device__ float g_Q[NSEQ * HID];
__device__ float g_K[NSEQ * HID];
__device__ float g_V[NSEQ * HID];
__device__ float g_O[NSEQ * HID];
__device__ float g_part[16 * HID];
__device__ float g_qbar[HID];
__device__ float g_imp[NH * NSEQ];
__device__ int   g_idx[NH * TOPK];

// ---------------- SGEMM: C = A(2048x2048) @ B(2048x2048) + bias ----------------
// BM=BN=128, BK=8, 256 threads, 8x8 per thread.
__global__ __launch_bounds__(256, 2)
void sgemm_bias(const float* __restrict__ A, const float* __restrict__ B,
                const float* __restrict__ bias, float* __restrict__ C) {
    __shared__ float As[8][128];
    __shared__ float Bs[8][128];
    const int tid = threadIdx.x;
    const int bx = blockIdx.x, by = blockIdx.y;
    const int tx = tid & 15, ty = tid >> 4;

    const int a_row = tid >> 1;
    const int a_col = (tid & 1) * 4;
    const int b_row = tid >> 5;
    const int b_col = (tid & 31) * 4;

    const float* Ap = A + (by * 128 + a_row) * HID + a_col;
    const float* Bp = B + b_row * HID + bx * 128 + b_col;

    float acc[8][8] = {};
    for (int k0 = 0; k0 < HID; k0 += 8) {
        float4 av = *(const float4*)(Ap + k0);
        float4 bv = *(const float4*)(Bp + k0 * HID);
        As[a_col + 0][a_row] = av.x;
        As[a_col + 1][a_row] = av.y;
        As[a_col + 2][a_row] = av.z;
        As[a_col + 3][a_row] = av.w;
        *(float4*)&Bs[b_row][b_col] = bv;
        __syncthreads();
#pragma unroll
        for (int kk = 0; kk < 8; ++kk) {
            float4 a0 = *(const float4*)&As[kk][ty * 8];
            float4 a1 = *(const float4*)&As[kk][ty * 8 + 4];
            float4 b0 = *(const float4*)&Bs[kk][tx * 8];
            float4 b1 = *(const float4*)&Bs[kk][tx * 8 + 4];
            float a[8] = {a0.x, a0.y, a0.z, a0.w, a1.x, a1.y, a1.z, a1.w};
            float b[8] = {b0.x, b0.y, b0.z, b0.w, b1.x, b1.y, b1.z, b1.w};
#pragma unroll
            for (int i = 0; i < 8; ++i)
#pragma unroll
                for (int j = 0; j < 8; ++j)
                    acc[i][j] = fmaf(a[i], b[j], acc[i][j]);
        }
        __syncthreads();
    }
#pragma unroll
    for (int i = 0; i < 8; ++i) {
        int row = by * 128 + ty * 8 + i;
        int col = bx * 128 + tx * 8;
        float4 o0, o1;
        o0.x = acc[i][0] + bias[col + 0];
        o0.y = acc[i][1] + bias[col + 1];
        o0.z = acc[i][2] + bias[col + 2];
        o0.w = acc[i][3] + bias[col + 3];
        o1.x = acc[i][4] + bias[col + 4];
        o1.y = acc[i][5] + bias[col + 5];
        o1.z = acc[i][6] + bias[col + 6];
        o1.w = acc[i][7] + bias[col + 7];
        *(float4*)&C[row * HID + col]     = o0;
        *(float4*)&C[row * HID + col + 4] = o1;
    }
}

// ---------------- column sum of Q (for qbar) ----------------
__global__ void colsum_part() {
    int c = blockIdx.x * 256 + threadIdx.x;      // 0..2047
    int chunk = blockIdx.y;                       // 0..15
    int n0 = chunk * 128;
    float s = 0.f;
#pragma unroll 8
    for (int n = 0; n < 128; ++n) s += g_Q[(n0 + n) * HID + c];
    g_part[chunk * HID + c] = s;
}

__global__ void colsum_final() {
    int c = blockIdx.x * 256 + threadIdx.x;
    float s = 0.f;
#pragma unroll
    for (int t = 0; t < 16; ++t) s += g_part[t * HID + c];
    g_qbar[c] = s;   // unnormalized, monotonic for ranking
}

// ---------------- importance[h, m] = qbar_h . k_m (one warp per (h,m)) ----------------
__global__ void imp_kernel() {
    int gw = (blockIdx.x * blockDim.x + threadIdx.x) >> 5;   // 0..32767
    int lane = threadIdx.x & 31;
    int h = gw >> 11, m = gw & 2047;
    float4 kv = *(const float4*)&g_K[(size_t)m * HID + h * HD + lane * 4];
    float4 qv = *(const float4*)&g_qbar[h * HD + lane * 4];
    float s = kv.x * qv.x + kv.y * qv.y + kv.z * qv.z + kv.w * qv.w;
#pragma unroll
    for (int o = 16; o; o >>= 1) s += __shfl_xor_sync(0xffffffffu, s, o);
    if (!lane) g_imp[h * NSEQ + m] = s;
}

// ---------------- top-k by rank counting (ties broken by lower index = jax) ----------------
__global__ void topk_kernel() {
    __shared__ float sv[NSEQ];
    __shared__ int scnt;
    int h = blockIdx.x, tid = threadIdx.x;
    if (tid == 0) scnt = 0;
    for (int i = tid; i < NSEQ; i += 256) sv[i] = g_imp[h * NSEQ + i];
    __syncthreads();
    const float4* p4 = (const float4*)sv;
#pragma unroll
    for (int e = 0; e < 8; ++e) {
        int m = e * 256 + tid;
        float v = sv[m];
        int rank = 0;
        for (int j4 = 0; j4 < NSEQ / 4; ++j4) {
            float4 x = p4[j4];
            int jb = j4 * 4;
            rank += (x.x > v) + (x.y > v) + (x.z > v) + (x.w > v);
            rank += (x.x == v && jb + 0 < m);
            rank += (x.y == v && jb + 1 < m);
            rank += (x.z == v && jb + 2 < m);
            rank += (x.w == v && jb + 3 < m);
        }
        if (rank < TOPK) {
            int pos = atomicAdd(&scnt, 1);   // order irrelevant: softmax is set-invariant
            g_idx[h * TOPK + pos] = m;
        }
    }
}

// ---------------- fused sparse attention ----------------
// block = (64-query tile, head). dyn smem:
//   Qs   [64][128]       floats  0     .. 8192
//   KT   [128][68] / Vc[64][128]  8192 .. 16896
//   S    [64][256]               16896 .. 33280
//   sidx int[256]                33280 .. 33536 (as floats)
#define ATTN_SMEM_BYTES ((33280 + 256) * 4)

__global__ __launch_bounds__(256, 1)
void attn_kernel() {
    extern __shared__ float sm[];
    float* Qs = sm;
    float* KT = sm + 8192;
    float* S  = sm + 16896;
    int* sidx = (int*)(sm + 33280);

    const int h  = blockIdx.y;
    const int n0 = blockIdx.x * 64;
    const int tid = threadIdx.x;
    const int tx = tid & 15, ty = tid >> 4;
    const int HB = h * HD;

    sidx[tid] = g_idx[h * TOPK + tid];
    for (int i = tid; i < 64 * 32; i += 256) {
        int q = i >> 5, dg = (i & 31) << 2;
        *(float4*)&Qs[q * 128 + dg] = *(const float4*)&g_Q[(size_t)(n0 + q) * HID + HB + dg];
    }
    __syncthreads();

    const float SCALE = 0.08838834764831845f;   // 1/sqrt(128)

    // ---- phase 1: S = scale * Q Ksel^T, chunks of 64 keys ----
    for (int kc = 0; kc < 4; ++kc) {
        if (kc) __syncthreads();
        for (int i = tid; i < 64 * 32; i += 256) {
            int j = i >> 5, dg = (i & 31) << 2;
            float4 kv = *(const float4*)&g_K[(size_t)sidx[kc * 64 + j] * HID + HB + dg];
            KT[(dg + 0) * 68 + j] = kv.x;
            KT[(dg + 1) * 68 + j] = kv.y;
            KT[(dg + 2) * 68 + j] = kv.z;
            KT[(dg + 3) * 68 + j] = kv.w;
        }
        __syncthreads();
        float acc[4][4] = {};
#pragma unroll 8
        for (int d = 0; d < 128; ++d) {
            float4 b = *(const float4*)&KT[d * 68 + tx * 4];
            float a0 = Qs[(ty * 4 + 0) * 128 + d];
            float a1 = Qs[(ty * 4 + 1) * 128 + d];
            float a2 = Qs[(ty * 4 + 2) * 128 + d];
            float a3 = Qs[(ty * 4 + 3) * 128 + d];
            acc[0][0] = fmaf(a0, b.x, acc[0][0]); acc[0][1] = fmaf(a0, b.y, acc[0][1]);
            acc[0][2] = fmaf(a0, b.z, acc[0][2]); acc[0][3] = fmaf(a0, b.w, acc[0][3]);
            acc[1][0] = fmaf(a1, b.x, acc[1][0]); acc[1][1] = fmaf(a1, b.y, acc[1][1]);
            acc[1][2] = fmaf(a1, b.z, acc[1][2]); acc[1][3] = fmaf(a1, b.w, acc[1][3]);
            acc[2][0] = fmaf(a2, b.x, acc[2][0]); acc[2][1] = fmaf(a2, b.y, acc[2][1]);
            acc[2][2] = fmaf(a2, b.z, acc[2][2]); acc[2][3] = fmaf(a2, b.w, acc[2][3]);
            acc[3][0] = fmaf(a3, b.x, acc[3][0]); acc[3][1] = fmaf(a3, b.y, acc[3][1]);
            acc[3][2] = fmaf(a3, b.z, acc[3][2]); acc[3][3] = fmaf(a3, b.w, acc[3][3]);
        }
#pragma unroll
        for (int i = 0; i < 4; ++i)
#pragma unroll
            for (int jj = 0; jj < 4; ++jj)
                S[(ty * 4 + i) * 256 + kc * 64 + tx * 4 + jj] = acc[i][jj] * SCALE;
    }
    __syncthreads();

    // ---- phase 2: row softmax over 256 keys (one warp / row) ----
    {
        int warp = tid >> 5, lane = tid & 31;
        for (int r = warp; r < 64; r += 8) {
            float vals[8], mx = -1e30f;
#pragma unroll
            for (int t = 0; t < 8; ++t) {
                vals[t] = S[r * 256 + lane + t * 32];
                mx = fmaxf(mx, vals[t]);
            }
#pragma unroll
            for (int o = 16; o; o >>= 1) mx = fmaxf(mx, __shfl_xor_sync(0xffffffffu, mx, o));
            float ssum = 0.f;
#pragma unroll
            for (int t = 0; t < 8; ++t) { vals[t] = expf(vals[t] - mx); ssum += vals[t]; }
#pragma unroll
            for (int o = 16; o; o >>= 1) ssum += __shfl_xor_sync(0xffffffffu, ssum, o);
            float inv = 1.0f / ssum;
#pragma unroll
            for (int t = 0; t < 8; ++t) S[r * 256 + lane + t * 32] = vals[t] * inv;
        }
    }

    // ---- phase 3: O = W @ Vsel, chunks of 64 keys (Vc reuses KT buffer) ----
    float oacc[4][8] = {};
    for (int kc = 0; kc < 4; ++kc) {
        __syncthreads();
        for (int i = tid; i < 64 * 32; i += 256) {
            int j = i >> 5, dg = (i & 31) << 2;
            *(float4*)&KT[j * 128 + dg] =
                *(const float4*)&g_V[(size_t)sidx[kc * 64 + j] * HID + HB + dg];
        }
        __syncthreads();
#pragma unroll 2
        for (int j = 0; j < 64; ++j) {
            float w0 = S[(ty * 4 + 0) * 256 + kc * 64 + j];
            float w1 = S[(ty * 4 + 1) * 256 + kc * 64 + j];
            float w2 = S[(ty * 4 + 2) * 256 + kc * 64 + j];
            float w3 = S[(ty * 4 + 3) * 256 + kc * 64 + j];
            float4 v0 = *(const float4*)&KT[j * 128 + tx * 8];
            float4 v1 = *(const float4*)&KT[j * 128 + tx * 8 + 4];
            oacc[0][0] = fmaf(w0, v0.x, oacc[0][0]); oacc[0][1] = fmaf(w0, v0.y, oacc[0][1]);
            oacc[0][2] = fmaf(w0, v0.z, oacc[0][2]); oacc[0][3] = fmaf(w0, v0.w, oacc[0][3]);
            oacc[0][4] = fmaf(w0, v1.x, oacc[0][4]); oacc[0][5] = fmaf(w0, v1.y, oacc[0][5]);
            oacc[0][6] = fmaf(w0, v1.z, oacc[0][6]); oacc[0][7] = fmaf(w0, v1.w, oacc[0][7]);
            oacc[1][0] = fmaf(w1, v0.x, oacc[1][0]); oacc[1][1] = fmaf(w1, v0.y, oacc[1][1]);
            oacc[1][2] = fmaf(w1, v0.z, oacc[1][2]); oacc[1][3] = fmaf(w1, v0.w, oacc[1][3]);
            oacc[1][4] = fmaf(w1, v1.x, oacc[1][4]); oacc[1][5] = fmaf(w1, v1.y, oacc[1][5]);
            oacc[1][6] = fmaf(w1, v1.z, oacc[1][6]); oacc[1][7] = fmaf(w1, v1.w, oacc[1][7]);
            oacc[2][0] = fmaf(w2, v0.x, oacc[2][0]); oacc[2][1] = fmaf(w2, v0.y, oacc[2][1]);
            oacc[2][2] = fmaf(w2, v0.z, oacc[2][2]); oacc[2][3] = fmaf(w2, v0.w, oacc[2][3]);
            oacc[2][4] = fmaf(w2, v1.x, oacc[2][4]); oacc[2][5] = fmaf(w2, v1.y, oacc[2][5]);
            oacc[2][6] = fmaf(w2, v1.z, oacc[2][6]); oacc[2][7] = fmaf(w2, v1.w, oacc[2][7]);
            oacc[3][0] = fmaf(w3, v0.x, oacc[3][0]); oacc[3][1] = fmaf(w3, v0.y, oacc[3][1]);
            oacc[3][2] = fmaf(w3, v0.z, oacc[3][2]); oacc[3][3] = fmaf(w3, v0.w, oacc[3][3]);
            oacc[3][4] = fmaf(w3, v1.x, oacc[3][4]); oacc[3][5] = fmaf(w3, v1.y, oacc[3][5]);
            oacc[3][6] = fmaf(w3, v1.z, oacc[3][6]); oacc[3][7] = fmaf(w3, v1.w, oacc[3][7]);
        }
    }
#pragma unroll
    for (int i = 0; i < 4; ++i) {
        float4 o0 = {oacc[i][0], oacc[i][1], oacc[i][2], oacc[i][3]};
        float4 o1 = {oacc[i][4], oacc[i][5], oacc[i][6], oacc[i][7]};
        size_t base = (size_t)(n0 + ty * 4 + i) * HID + HB + tx * 8;
        *(float4*)&g_O[base]     = o0;
        *(float4*)&g_O[base + 4] = o1;
    }
}

// ---------------- launch ----------------
extern "C" void kernel_launch(void* const* d_in, const int* in_sizes, int n_in,
                              void* d_out, int out_size) {
    const float* X  = (const float*)d_in[0];
    const float* Wq = (const float*)d_in[1];
    const float* bq = (const float*)d_in[2];
    const float* Wk = (const float*)d_in[3];
    const float* bk = (const float*)d_in[4];
    const float* Wv = (const float*)d_in[5];
    const float* bv = (const float*)d_in[6];
    const float* Wo = (const float*)d_in[7];
    const float* bo = (const float*)d_in[8];
    float* out = (float*)d_out;

    float *Qd, *Kd, *Vd, *Od;
    cudaGetSymbolAddress((void**)&Qd, g_Q);
    cudaGetSymbolAddress((void**)&Kd, g_K);
    cudaGetSymbolAddress((void**)&Vd, g_V);
    cudaGetSymbolAddress((void**)&Od, g_O);

    static bool attr_done = false;
    if (!attr_done) {
        cudaFuncSetAttribute(attn_kernel, cudaFuncAttributeMaxDynamicSharedMemorySize,
                             ATTN_SMEM_BYTES);
        attr_done = true;
    }

    dim3 gg(16, 16);
    sgemm_bias<<<gg, 256>>>(X, Wq, bq, Qd);
    sgemm_bias<<<gg, 256>>>(X, Wk, bk, Kd);
    sgemm_bias<<<gg, 256>>>(X, Wv, bv, Vd);

    colsum_part<<<dim3(8, 16), 256>>>();
    colsum_final<<<8, 256>>>();
    imp_kernel<<<4096, 256>>>();
    topk_kernel<<<16, 256>>>();

    attn_kernel<<<dim3(32, 16), 256, ATTN_SMEM_BYTES>>>();

    sgemm_bias<<<gg, 256>>>(Od, Wo, bo, out);
}

// round 3
// speedup vs baseline: 2.1629x; 2.1629x over previous
#include <cuda_runtime.h>
#include <cuda_bf16.h>
#include <math.h>
#include <stdint.h>

#define HID  2048
#define NSEQ 2048
#define NH   16
#define HD   128
#define TOPK 256

// ---------------- scratch (device globals; no allocation) ----------------
__device__ float g_Q[NSEQ * HID];
__device__ float g_K[NSEQ * HID];
__device__ float g_V[NSEQ * HID];
__device__ float g_O[NSEQ * HID];
__device__ float g_part[16 * HID];
__device__ float g_qbar[HID];
__device__ float g_imp[NH * NSEQ];
__device__ int   g_idx[NH * TOPK];

__device__ __align__(16) __nv_bfloat16 g_Xh[NSEQ * HID];
__device__ __align__(16) __nv_bfloat16 g_Xl[NSEQ * HID];
__device__ __align__(16) __nv_bfloat16 g_Oh[NSEQ * HID];
__device__ __align__(16) __nv_bfloat16 g_Ol[NSEQ * HID];
__device__ __align__(16) __nv_bfloat16 g_Wh[4][HID * HID];   // W^T splits, [N][K]
__device__ __align__(16) __nv_bfloat16 g_Wl[4][HID * HID];

// ======================= small PTX helpers (all plain sm_103-safe) =======================
__device__ __forceinline__ void ldsm4(uint32_t addr, uint32_t* r) {
    asm volatile("ldmatrix.sync.aligned.m8n8.x4.shared.b16 {%0,%1,%2,%3}, [%4];"
                 : "=r"(r[0]), "=r"(r[1]), "=r"(r[2]), "=r"(r[3]) : "r"(addr));
}
__device__ __forceinline__ void mma16816(float* d, const uint32_t* a, uint32_t b0, uint32_t b1) {
    asm volatile("mma.sync.aligned.m16n8k16.row.col.f32.bf16.bf16.f32 "
                 "{%0,%1,%2,%3}, {%4,%5,%6,%7}, {%8,%9}, {%0,%1,%2,%3};"
                 : "+f"(d[0]), "+f"(d[1]), "+f"(d[2]), "+f"(d[3])
                 : "r"(a[0]), "r"(a[1]), "r"(a[2]), "r"(a[3]), "r"(b0), "r"(b1));
}
#define CP16(dst, src) \
    asm volatile("cp.async.cg.shared.global [%0], [%1], 16;" :: "r"(dst), "l"(src))
#define CP_COMMIT() asm volatile("cp.async.commit_group;" ::: "memory")
#define CP_WAIT1()  asm volatile("cp.async.wait_group 1;" ::: "memory")
#define CP_WAIT0()  asm volatile("cp.async.wait_group 0;" ::: "memory")

// ======================= split / transpose-split =======================
__global__ void split_f32(const float* __restrict__ x,
                          __nv_bfloat16* __restrict__ hi, __nv_bfloat16* __restrict__ lo) {
    int i = (blockIdx.x * 256 + threadIdx.x) * 4;
    float4 v = *(const float4*)(x + i);
    __nv_bfloat16 h0 = __float2bfloat16(v.x);
    __nv_bfloat16 h1 = __float2bfloat16(v.y);
    __nv_bfloat16 h2 = __float2bfloat16(v.z);
    __nv_bfloat16 h3 = __float2bfloat16(v.w);
    ushort4 hv = {__bfloat16_as_ushort(h0), __bfloat16_as_ushort(h1),
                  __bfloat16_as_ushort(h2), __bfloat16_as_ushort(h3)};
    __nv_bfloat16 l0 = __float2bfloat16(v.x - __bfloat162float(h0));
    __nv_bfloat16 l1 = __float2bfloat16(v.y - __bfloat162float(h1));
    __nv_bfloat16 l2 = __float2bfloat16(v.z - __bfloat162float(h2));
    __nv_bfloat16 l3 = __float2bfloat16(v.w - __bfloat162float(h3));
    ushort4 lv = {__bfloat16_as_ushort(l0), __bfloat16_as_ushort(l1),
                  __bfloat16_as_ushort(l2), __bfloat16_as_ushort(l3)};
    *(ushort4*)(hi + i) = hv;
    *(ushort4*)(lo + i) = lv;
}

// W [K][N] row-major fp32  ->  T_hi/T_lo [N][K] bf16
__global__ void transpose_split(const float* __restrict__ W,
                                __nv_bfloat16* __restrict__ Th, __nv_bfloat16* __restrict__ Tl) {
    __shared__ float t[32][33];
    int n0 = blockIdx.x * 32, k0 = blockIdx.y * 32;
    int tx = threadIdx.x, ty = threadIdx.y;  // block (32, 8)
#pragma unroll
    for (int j = 0; j < 32; j += 8)
        t[ty + j][tx] = W[(size_t)(k0 + ty + j) * HID + n0 + tx];
    __syncthreads();
#pragma unroll
    for (int j = 0; j < 32; j += 8) {
        float v = t[tx][ty + j];
        __nv_bfloat16 h = __float2bfloat16(v);
        size_t o = (size_t)(n0 + ty + j) * HID + k0 + tx;
        Th[o] = h;
        Tl[o] = __float2bfloat16(v - __bfloat162float(h));
    }
}

// ======================= HMMA bf16x3 GEMM =======================
// C[2048,2048] = (Ah+Al)[M,K] @ (Bh+Bl)^T ([N,K] storage) + bias
// CTA tile 128x128, BK=64, 8 warps (warp tile 32x64), double-buffered cp.async.
// Stage layout: Ah | Al | Bh | Bl, each 128x64 bf16 = 16KB, swizzled 128B rows.
#define GSMEM (2 * 4 * 16384)

__global__ __launch_bounds__(256, 1)
void gemm_bf16x3(const __nv_bfloat16* __restrict__ Ah, const __nv_bfloat16* __restrict__ Al,
                 const __nv_bfloat16* __restrict__ Bh, const __nv_bfloat16* __restrict__ Bl,
                 const float* __restrict__ bias, float* __restrict__ C) {
    extern __shared__ char smem[];
    const uint32_t sb = (uint32_t)__cvta_generic_to_shared(smem);
    const int tid = threadIdx.x, lane = tid & 31, wid = tid >> 5;
    const int m0 = blockIdx.y * 128, n0 = blockIdx.x * 128;
    const int wm = (wid >> 1) * 32, wn = (wid & 1) * 64;

    const __nv_bfloat16* tsrc[4] = {
        Ah + (size_t)m0 * HID, Al + (size_t)m0 * HID,
        Bh + (size_t)n0 * HID, Bl + (size_t)n0 * HID};

    // per-thread copy map: 4 chunk-ids per tile
    const int cid0 = tid;            // id = cid0 + j*256, r = id>>3, c = id&7

    float d[16][4];                  // [f*8 + j][4]
#pragma unroll
    for (int i = 0; i < 16; ++i) { d[i][0] = d[i][1] = d[i][2] = d[i][3] = 0.f; }

    // precompute ldmatrix address components
    const int grp = lane >> 3, lr = lane & 7;
    // A: row = wm + f*16 + (grp&1)*8 + lr ; chunk = ks*2 + (grp>>1)
    // B: row = wn + jn*16 + (grp>>1)*8 + lr ; chunk = ks*2 + (grp&1)
    const int arow_b = wm + (grp & 1) * 8 + lr;
    const int brow_b = wn + (grp >> 1) * 8 + lr;
    const int akc_b = grp >> 1;
    const int bkc_b = grp & 1;

    // ---------------- prologue: stage 0 ----------------
    {
        int k0 = 0;
#pragma unroll
        for (int j = 0; j < 4; ++j) {
            int id = cid0 + j * 256;
            int r = id >> 3, c = id & 7;
            uint32_t doff = (uint32_t)(r * 128 + ((c ^ (r & 7)) << 4));
#pragma unroll
            for (int t = 0; t < 4; ++t)
                CP16(sb + t * 16384 + doff, tsrc[t] + (size_t)r * HID + k0 + c * 8);
        }
        CP_COMMIT();
    }

    for (int kc = 0; kc < 32; ++kc) {
        if (kc + 1 < 32) {
            int k0 = (kc + 1) * 64;
            uint32_t sbase = sb + ((kc + 1) & 1) * 65536;
#pragma unroll
            for (int j = 0; j < 4; ++j) {
                int id = cid0 + j * 256;
                int r = id >> 3, c = id & 7;
                uint32_t doff = (uint32_t)(r * 128 + ((c ^ (r & 7)) << 4));
#pragma unroll
                for (int t = 0; t < 4; ++t)
                    CP16(sbase + t * 16384 + doff, tsrc[t] + (size_t)r * HID + k0 + c * 8);
            }
            CP_COMMIT();
            CP_WAIT1();
        } else {
            CP_WAIT0();
        }
        __syncthreads();

        const uint32_t base = sb + (kc & 1) * 65536;
        const uint32_t TAh = base, TAl = base + 16384, TBh = base + 32768, TBl = base + 49152;

#pragma unroll
        for (int ks = 0; ks < 4; ++ks) {
            uint32_t aH[2][4], aL[2][4], bH[4][4], bL[4][4];
#pragma unroll
            for (int f = 0; f < 2; ++f) {
                int row = arow_b + f * 16;
                int kc8 = ks * 2 + akc_b;
                uint32_t off = (uint32_t)(row * 128 + ((kc8 ^ (row & 7)) << 4));
                ldsm4(TAh + off, aH[f]);
                ldsm4(TAl + off, aL[f]);
            }
#pragma unroll
            for (int jn = 0; jn < 4; ++jn) {
                int row = brow_b + jn * 16;
                int kc8 = ks * 2 + bkc_b;
                uint32_t off = (uint32_t)(row * 128 + ((kc8 ^ (row & 7)) << 4));
                ldsm4(TBh + off, bH[jn]);
                ldsm4(TBl + off, bL[jn]);
            }
#pragma unroll
            for (int f = 0; f < 2; ++f) {
#pragma unroll
                for (int jn = 0; jn < 4; ++jn) {
#pragma unroll
                    for (int sub = 0; sub < 2; ++sub) {
                        float* dd = d[f * 8 + jn * 2 + sub];
                        uint32_t h0 = bH[jn][sub * 2], h1 = bH[jn][sub * 2 + 1];
                        mma16816(dd, aH[f], h0, h1);                                  // Ah*Bh
                        mma16816(dd, aH[f], bL[jn][sub * 2], bL[jn][sub * 2 + 1]);    // Ah*Bl
                        mma16816(dd, aL[f], h0, h1);                                  // Al*Bh
                    }
                }
            }
        }
        __syncthreads();
    }

    // ---------------- epilogue ----------------
    const int rq = lane >> 2, cq = (lane & 3) * 2;
#pragma unroll
    for (int j = 0; j < 8; ++j) {
        int col = n0 + wn + j * 8 + cq;
        float2 bb = *(const float2*)&bias[col];
#pragma unroll
        for (int f = 0; f < 2; ++f) {
            const float* dd = d[f * 8 + j];
            int row = m0 + wm + f * 16 + rq;
            float2 o0 = {dd[0] + bb.x, dd[1] + bb.y};
            float2 o1 = {dd[2] + bb.x, dd[3] + bb.y};
            *(float2*)&C[(size_t)row * HID + col]       = o0;
            *(float2*)&C[(size_t)(row + 8) * HID + col] = o1;
        }
    }
}

// ---------------- column sum of Q (for qbar) ----------------
__global__ void colsum_part() {
    int c = blockIdx.x * 256 + threadIdx.x;
    int chunk = blockIdx.y;
    int n0 = chunk * 128;
    float s = 0.f;
#pragma unroll 8
    for (int n = 0; n < 128; ++n) s += g_Q[(n0 + n) * HID + c];
    g_part[chunk * HID + c] = s;
}

__global__ void colsum_final() {
    int c = blockIdx.x * 256 + threadIdx.x;
    float s = 0.f;
#pragma unroll
    for (int t = 0; t < 16; ++t) s += g_part[t * HID + c];
    g_qbar[c] = s;
}

// ---------------- importance[h, m] = qbar_h . k_m ----------------
__global__ void imp_kernel() {
    int gw = (blockIdx.x * blockDim.x + threadIdx.x) >> 5;
    int lane = threadIdx.x & 31;
    int h = gw >> 11, m = gw & 2047;
    float4 kv = *(const float4*)&g_K[(size_t)m * HID + h * HD + lane * 4];
    float4 qv = *(const float4*)&g_qbar[h * HD + lane * 4];
    float s = kv.x * qv.x + kv.y * qv.y + kv.z * qv.z + kv.w * qv.w;
#pragma unroll
    for (int o = 16; o; o >>= 1) s += __shfl_xor_sync(0xffffffffu, s, o);
    if (!lane) g_imp[h * NSEQ + m] = s;
}

// ---------------- top-k by rank counting ----------------
__global__ void topk_kernel() {
    __shared__ float sv[NSEQ];
    __shared__ int scnt;
    int h = blockIdx.x, tid = threadIdx.x;
    if (tid == 0) scnt = 0;
    for (int i = tid; i < NSEQ; i += 256) sv[i] = g_imp[h * NSEQ + i];
    __syncthreads();
    const float4* p4 = (const float4*)sv;
#pragma unroll
    for (int e = 0; e < 8; ++e) {
        int m = e * 256 + tid;
        float v = sv[m];
        int rank = 0;
        for (int j4 = 0; j4 < NSEQ / 4; ++j4) {
            float4 x = p4[j4];
            int jb = j4 * 4;
            rank += (x.x > v) + (x.y > v) + (x.z > v) + (x.w > v);
            rank += (x.x == v && jb + 0 < m);
            rank += (x.y == v && jb + 1 < m);
            rank += (x.z == v && jb + 2 < m);
            rank += (x.w == v && jb + 3 < m);
        }
        if (rank < TOPK) {
            int pos = atomicAdd(&scnt, 1);
            g_idx[h * TOPK + pos] = m;
        }
    }
}

// ---------------- fused sparse attention ----------------
#define ATTN_SMEM_BYTES ((33280 + 256) * 4)

__global__ __launch_bounds__(256, 1)
void attn_kernel() {
    extern __shared__ float sm[];
    float* Qs = sm;
    float* KT = sm + 8192;
    float* S  = sm + 16896;
    int* sidx = (int*)(sm + 33280);

    const int h  = blockIdx.y;
    const int n0 = blockIdx.x * 64;
    const int tid = threadIdx.x;
    const int tx = tid & 15, ty = tid >> 4;
    const int HB = h * HD;

    sidx[tid] = g_idx[h * TOPK + tid];
    for (int i = tid; i < 64 * 32; i += 256) {
        int q = i >> 5, dg = (i & 31) << 2;
        *(float4*)&Qs[q * 128 + dg] = *(const float4*)&g_Q[(size_t)(n0 + q) * HID + HB + dg];
    }
    __syncthreads();

    const float SCALE = 0.08838834764831845f;

    for (int kc = 0; kc < 4; ++kc) {
        if (kc) __syncthreads();
        for (int i = tid; i < 64 * 32; i += 256) {
            int j = i >> 5, dg = (i & 31) << 2;
            float4 kv = *(const float4*)&g_K[(size_t)sidx[kc * 64 + j] * HID + HB + dg];
            KT[(dg + 0) * 68 + j] = kv.x;
            KT[(dg + 1) * 68 + j] = kv.y;
            KT[(dg + 2) * 68 + j] = kv.z;
            KT[(dg + 3) * 68 + j] = kv.w;
        }
        __syncthreads();
        float acc[4][4] = {};
#pragma unroll 8
        for (int d = 0; d < 128; ++d) {
            float4 b = *(const float4*)&KT[d * 68 + tx * 4];
            float a0 = Qs[(ty * 4 + 0) * 128 + d];
            float a1 = Qs[(ty * 4 + 1) * 128 + d];
            float a2 = Qs[(ty * 4 + 2) * 128 + d];
            float a3 = Qs[(ty * 4 + 3) * 128 + d];
            acc[0][0] = fmaf(a0, b.x, acc[0][0]); acc[0][1] = fmaf(a0, b.y, acc[0][1]);
            acc[0][2] = fmaf(a0, b.z, acc[0][2]); acc[0][3] = fmaf(a0, b.w, acc[0][3]);
            acc[1][0] = fmaf(a1, b.x, acc[1][0]); acc[1][1] = fmaf(a1, b.y, acc[1][1]);
            acc[1][2] = fmaf(a1, b.z, acc[1][2]); acc[1][3] = fmaf(a1, b.w, acc[1][3]);
            acc[2][0] = fmaf(a2, b.x, acc[2][0]); acc[2][1] = fmaf(a2, b.y, acc[2][1]);
            acc[2][2] = fmaf(a2, b.z, acc[2][2]); acc[2][3] = fmaf(a2, b.w, acc[2][3]);
            acc[3][0] = fmaf(a3, b.x, acc[3][0]); acc[3][1] = fmaf(a3, b.y, acc[3][1]);
            acc[3][2] = fmaf(a3, b.z, acc[3][2]); acc[3][3] = fmaf(a3, b.w, acc[3][3]);
        }
#pragma unroll
        for (int i = 0; i < 4; ++i)
#pragma unroll
            for (int jj = 0; jj < 4; ++jj)
                S[(ty * 4 + i) * 256 + kc * 64 + tx * 4 + jj] = acc[i][jj] * SCALE;
    }
    __syncthreads();

    {
        int warp = tid >> 5, lane = tid & 31;
        for (int r = warp; r < 64; r += 8) {
            float vals[8], mx = -1e30f;
#pragma unroll
            for (int t = 0; t < 8; ++t) {
                vals[t] = S[r * 256 + lane + t * 32];
                mx = fmaxf(mx, vals[t]);
            }
#pragma unroll
            for (int o = 16; o; o >>= 1) mx = fmaxf(mx, __shfl_xor_sync(0xffffffffu, mx, o));
            float ssum = 0.f;
#pragma unroll
            for (int t = 0; t < 8; ++t) { vals[t] = expf(vals[t] - mx); ssum += vals[t]; }
#pragma unroll
            for (int o = 16; o; o >>= 1) ssum += __shfl_xor_sync(0xffffffffu, ssum, o);
            float inv = 1.0f / ssum;
#pragma unroll
            for (int t = 0; t < 8; ++t) S[r * 256 + lane + t * 32] = vals[t] * inv;
        }
    }

    float oacc[4][8] = {};
    for (int kc = 0; kc < 4; ++kc) {
        __syncthreads();
        for (int i = tid; i < 64 * 32; i += 256) {
            int j = i >> 5, dg = (i & 31) << 2;
            *(float4*)&KT[j * 128 + dg] =
                *(const float4*)&g_V[(size_t)sidx[kc * 64 + j] * HID + HB + dg];
        }
        __syncthreads();
#pragma unroll 2
        for (int j = 0; j < 64; ++j) {
            float w0 = S[(ty * 4 + 0) * 256 + kc * 64 + j];
            float w1 = S[(ty * 4 + 1) * 256 + kc * 64 + j];
            float w2 = S[(ty * 4 + 2) * 256 + kc * 64 + j];
            float w3 = S[(ty * 4 + 3) * 256 + kc * 64 + j];
            float4 v0 = *(const float4*)&KT[j * 128 + tx * 8];
            float4 v1 = *(const float4*)&KT[j * 128 + tx * 8 + 4];
            oacc[0][0] = fmaf(w0, v0.x, oacc[0][0]); oacc[0][1] = fmaf(w0, v0.y, oacc[0][1]);
            oacc[0][2] = fmaf(w0, v0.z, oacc[0][2]); oacc[0][3] = fmaf(w0, v0.w, oacc[0][3]);
            oacc[0][4] = fmaf(w0, v1.x, oacc[0][4]); oacc[0][5] = fmaf(w0, v1.y, oacc[0][5]);
            oacc[0][6] = fmaf(w0, v1.z, oacc[0][6]); oacc[0][7] = fmaf(w0, v1.w, oacc[0][7]);
            oacc[1][0] = fmaf(w1, v0.x, oacc[1][0]); oacc[1][1] = fmaf(w1, v0.y, oacc[1][1]);
            oacc[1][2] = fmaf(w1, v0.z, oacc[1][2]); oacc[1][3] = fmaf(w1, v0.w, oacc[1][3]);
            oacc[1][4] = fmaf(w1, v1.x, oacc[1][4]); oacc[1][5] = fmaf(w1, v1.y, oacc[1][5]);
            oacc[1][6] = fmaf(w1, v1.z, oacc[1][6]); oacc[1][7] = fmaf(w1, v1.w, oacc[1][7]);
            oacc[2][0] = fmaf(w2, v0.x, oacc[2][0]); oacc[2][1] = fmaf(w2, v0.y, oacc[2][1]);
            oacc[2][2] = fmaf(w2, v0.z, oacc[2][2]); oacc[2][3] = fmaf(w2, v0.w, oacc[2][3]);
            oacc[2][4] = fmaf(w2, v1.x, oacc[2][4]); oacc[2][5] = fmaf(w2, v1.y, oacc[2][5]);
            oacc[2][6] = fmaf(w2, v1.z, oacc[2][6]); oacc[2][7] = fmaf(w2, v1.w, oacc[2][7]);
            oacc[3][0] = fmaf(w3, v0.x, oacc[3][0]); oacc[3][1] = fmaf(w3, v0.y, oacc[3][1]);
            oacc[3][2] = fmaf(w3, v0.z, oacc[3][2]); oacc[3][3] = fmaf(w3, v0.w, oacc[3][3]);
            oacc[3][4] = fmaf(w3, v1.x, oacc[3][4]); oacc[3][5] = fmaf(w3, v1.y, oacc[3][5]);
            oacc[3][6] = fmaf(w3, v1.z, oacc[3][6]); oacc[3][7] = fmaf(w3, v1.w, oacc[3][7]);
        }
    }
#pragma unroll
    for (int i = 0; i < 4; ++i) {
        float4 o0 = {oacc[i][0], oacc[i][1], oacc[i][2], oacc[i][3]};
        float4 o1 = {oacc[i][4], oacc[i][5], oacc[i][6], oacc[i][7]};
        size_t base = (size_t)(n0 + ty * 4 + i) * HID + HB + tx * 8;
        *(float4*)&g_O[base]     = o0;
        *(float4*)&g_O[base + 4] = o1;
    }
}

// ======================= host =======================
extern "C" void kernel_launch(void* const* d_in, const int* in_sizes, int n_in,
                              void* d_out, int out_size) {
    const float* X  = (const float*)d_in[0];
    const float* Wq = (const float*)d_in[1];
    const float* bq = (const float*)d_in[2];
    const float* Wk = (const float*)d_in[3];
    const float* bk = (const float*)d_in[4];
    const float* Wv = (const float*)d_in[5];
    const float* bv = (const float*)d_in[6];
    const float* Wo = (const float*)d_in[7];
    const float* bo = (const float*)d_in[8];
    float* out = (float*)d_out;

    float *Qd, *Kd, *Vd, *Od;
    __nv_bfloat16 *Xh, *Xl, *Oh, *Ol, *Wh, *Wl;
    cudaGetSymbolAddress((void**)&Qd, g_Q);
    cudaGetSymbolAddress((void**)&Kd, g_K);
    cudaGetSymbolAddress((void**)&Vd, g_V);
    cudaGetSymbolAddress((void**)&Od, g_O);
    cudaGetSymbolAddress((void**)&Xh, g_Xh);
    cudaGetSymbolAddress((void**)&Xl, g_Xl);
    cudaGetSymbolAddress((void**)&Oh, g_Oh);
    cudaGetSymbolAddress((void**)&Ol, g_Ol);
    cudaGetSymbolAddress((void**)&Wh, g_Wh);
    cudaGetSymbolAddress((void**)&Wl, g_Wl);

    cudaFuncSetAttribute(attn_kernel, cudaFuncAttributeMaxDynamicSharedMemorySize,
                         ATTN_SMEM_BYTES);
    cudaFuncSetAttribute(gemm_bf16x3, cudaFuncAttributeMaxDynamicSharedMemorySize, GSMEM);

    const size_t WSZ = (size_t)HID * HID;

    // split X; transpose+split weights
    split_f32<<<4096, 256>>>(X, Xh, Xl);
    transpose_split<<<dim3(64, 64), dim3(32, 8)>>>(Wq, Wh + 0 * WSZ, Wl + 0 * WSZ);
    transpose_split<<<dim3(64, 64), dim3(32, 8)>>>(Wk, Wh + 1 * WSZ, Wl + 1 * WSZ);
    transpose_split<<<dim3(64, 64), dim3(32, 8)>>>(Wv, Wh + 2 * WSZ, Wl + 2 * WSZ);
    transpose_split<<<dim3(64, 64), dim3(32, 8)>>>(Wo, Wh + 3 * WSZ, Wl + 3 * WSZ);

    dim3 gg(16, 16);  // n-tiles x m-tiles (128x128)
    gemm_bf16x3<<<gg, 256, GSMEM>>>(Xh, Xl, Wh + 0 * WSZ, Wl + 0 * WSZ, bq, Qd);
    gemm_bf16x3<<<gg, 256, GSMEM>>>(Xh, Xl, Wh + 1 * WSZ, Wl + 1 * WSZ, bk, Kd);
    gemm_bf16x3<<<gg, 256, GSMEM>>>(Xh, Xl, Wh + 2 * WSZ, Wl + 2 * WSZ, bv, Vd);

    colsum_part<<<dim3(8, 16), 256>>>();
    colsum_final<<<8, 256>>>();
    imp_kernel<<<4096, 256>>>();
    topk_kernel<<<16, 256>>>();

    attn_kernel<<<dim3(32, 16), 256, ATTN_SMEM_BYTES>>>();

    split_f32<<<4096, 256>>>(Od, Oh, Ol);
    gemm_bf16x3<<<gg, 256, GSMEM>>>(Oh, Ol, Wh + 3 * WSZ, Wl + 3 * WSZ, bo, out);
}

// round 5
// speedup vs baseline: 2.6335x; 1.2176x over previous
#include <cuda_runtime.h>
#include <cuda_bf16.h>
#include <math.h>
#include <stdint.h>

#define HID  2048
#define NSEQ 2048
#define NH   16
#define HD   128
#define TOPK 256

// ---------------- scratch (device globals; no allocation) ----------------
__device__ float g_Q[NSEQ * HID];
__device__ float g_K[NSEQ * HID];
__device__ float g_V[NSEQ * HID];
__device__ float g_part[16 * HID];
__device__ float g_qbar[HID];
__device__ float g_imp[NH * NSEQ];
__device__ int   g_idx[NH * TOPK];

__device__ __align__(16) __nv_bfloat16 g_Xh[NSEQ * HID];
__device__ __align__(16) __nv_bfloat16 g_Xl[NSEQ * HID];
__device__ __align__(16) __nv_bfloat16 g_Oh[NSEQ * HID];
__device__ __align__(16) __nv_bfloat16 g_Ol[NSEQ * HID];
__device__ __align__(16) __nv_bfloat16 g_Qh[NSEQ * HID];
__device__ __align__(16) __nv_bfloat16 g_Ql[NSEQ * HID];
__device__ __align__(16) __nv_bfloat16 g_Kh[NSEQ * HID];
__device__ __align__(16) __nv_bfloat16 g_Kl[NSEQ * HID];
__device__ __align__(16) __nv_bfloat16 g_Vh[NSEQ * HID];
__device__ __align__(16) __nv_bfloat16 g_Vl[NSEQ * HID];
__device__ __align__(16) __nv_bfloat16 g_Wh[4][HID * HID];   // W^T splits, [N][K]
__device__ __align__(16) __nv_bfloat16 g_Wl[4][HID * HID];

// ======================= PTX helpers (plain sm_103-safe) =======================
__device__ __forceinline__ void ldsm4(uint32_t addr, uint32_t* r) {
    asm volatile("ldmatrix.sync.aligned.m8n8.x4.shared.b16 {%0,%1,%2,%3}, [%4];"
                 : "=r"(r[0]), "=r"(r[1]), "=r"(r[2]), "=r"(r[3]) : "r"(addr));
}
__device__ __forceinline__ void ldsm4t(uint32_t addr, uint32_t* r) {
    asm volatile("ldmatrix.sync.aligned.m8n8.x4.trans.shared.b16 {%0,%1,%2,%3}, [%4];"
                 : "=r"(r[0]), "=r"(r[1]), "=r"(r[2]), "=r"(r[3]) : "r"(addr));
}
__device__ __forceinline__ void mma16816(float* d, const uint32_t* a, uint32_t b0, uint32_t b1) {
    asm volatile("mma.sync.aligned.m16n8k16.row.col.f32.bf16.bf16.f32 "
                 "{%0,%1,%2,%3}, {%4,%5,%6,%7}, {%8,%9}, {%0,%1,%2,%3};"
                 : "+f"(d[0]), "+f"(d[1]), "+f"(d[2]), "+f"(d[3])
                 : "r"(a[0]), "r"(a[1]), "r"(a[2]), "r"(a[3]), "r"(b0), "r"(b1));
}
#define CP16(dst, src) \
    asm volatile("cp.async.cg.shared.global [%0], [%1], 16;" :: "r"(dst), "l"(src))
#define CP_COMMIT() asm volatile("cp.async.commit_group;" ::: "memory")
#define CP_WAIT1()  asm volatile("cp.async.wait_group 1;" ::: "memory")
#define CP_WAIT0()  asm volatile("cp.async.wait_group 0;" ::: "memory")

__device__ __forceinline__ void split_store(__nv_bfloat16* Ch, __nv_bfloat16* Cl,
                                            int row, int col, float2 v) {
    __nv_bfloat16 h0 = __float2bfloat16(v.x), h1 = __float2bfloat16(v.y);
    uint32_t hw = (uint32_t)__bfloat16_as_ushort(h0) |
                  ((uint32_t)__bfloat16_as_ushort(h1) << 16);
    __nv_bfloat16 l0 = __float2bfloat16(v.x - __bfloat162float(h0));
    __nv_bfloat16 l1 = __float2bfloat16(v.y - __bfloat162float(h1));
    uint32_t lw = (uint32_t)__bfloat16_as_ushort(l0) |
                  ((uint32_t)__bfloat16_as_ushort(l1) << 16);
    *(uint32_t*)&Ch[(size_t)row * HID + col] = hw;
    *(uint32_t*)&Cl[(size_t)row * HID + col] = lw;
}

// ======================= split / transpose-split =======================
__global__ void split_f32(const float* __restrict__ x,
                          __nv_bfloat16* __restrict__ hi, __nv_bfloat16* __restrict__ lo) {
    int i = (blockIdx.x * 256 + threadIdx.x) * 4;
    float4 v = *(const float4*)(x + i);
    __nv_bfloat16 h0 = __float2bfloat16(v.x);
    __nv_bfloat16 h1 = __float2bfloat16(v.y);
    __nv_bfloat16 h2 = __float2bfloat16(v.z);
    __nv_bfloat16 h3 = __float2bfloat16(v.w);
    ushort4 hv = {__bfloat16_as_ushort(h0), __bfloat16_as_ushort(h1),
                  __bfloat16_as_ushort(h2), __bfloat16_as_ushort(h3)};
    __nv_bfloat16 l0 = __float2bfloat16(v.x - __bfloat162float(h0));
    __nv_bfloat16 l1 = __float2bfloat16(v.y - __bfloat162float(h1));
    __nv_bfloat16 l2 = __float2bfloat16(v.z - __bfloat162float(h2));
    __nv_bfloat16 l3 = __float2bfloat16(v.w - __bfloat162float(h3));
    ushort4 lv = {__bfloat16_as_ushort(l0), __bfloat16_as_ushort(l1),
                  __bfloat16_as_ushort(l2), __bfloat16_as_ushort(l3)};
    *(ushort4*)(hi + i) = hv;
    *(ushort4*)(lo + i) = lv;
}

// all 4 weights: [K][N] fp32 -> [N][K] bf16 hi/lo
__global__ void transpose_split4(const float* __restrict__ W0, const float* __restrict__ W1,
                                 const float* __restrict__ W2, const float* __restrict__ W3) {
    __shared__ float t[32][33];
    const float* W = blockIdx.z == 0 ? W0 : blockIdx.z == 1 ? W1 : blockIdx.z == 2 ? W2 : W3;
    __nv_bfloat16* Th = g_Wh[blockIdx.z];
    __nv_bfloat16* Tl = g_Wl[blockIdx.z];
    int n0 = blockIdx.x * 32, k0 = blockIdx.y * 32;
    int tx = threadIdx.x, ty = threadIdx.y;  // block (32, 8)
#pragma unroll
    for (int j = 0; j < 32; j += 8)
        t[ty + j][tx] = W[(size_t)(k0 + ty + j) * HID + n0 + tx];
    __syncthreads();
#pragma unroll
    for (int j = 0; j < 32; j += 8) {
        float v = t[tx][ty + j];
        __nv_bfloat16 h = __float2bfloat16(v);
        size_t o = (size_t)(n0 + ty + j) * HID + k0 + tx;
        Th[o] = h;
        Tl[o] = __float2bfloat16(v - __bfloat162float(h));
    }
}

// ======================= HMMA bf16x3 GEMM (3-stage pipeline) =======================
// C = (Ah+Al)[M,K] @ (Bh+Bl)^T ([N,K]) + bias. CTA 128x128, BK=64, 8 warps (32x64).
// Stage: Ah|Al|Bh|Bl (16KB each) = 64KB; 3 stages = 192KB.
#define GSMEM (3 * 65536)

__global__ __launch_bounds__(256, 1)
void gemm_bf16x3(const __nv_bfloat16* __restrict__ Ah, const __nv_bfloat16* __restrict__ Al,
                 const __nv_bfloat16* __restrict__ Bh, const __nv_bfloat16* __restrict__ Bl,
                 const float* __restrict__ bias, float* __restrict__ C,
                 __nv_bfloat16* __restrict__ Ch, __nv_bfloat16* __restrict__ Cl) {
    extern __shared__ char smem[];
    const uint32_t sb = (uint32_t)__cvta_generic_to_shared(smem);
    const int tid = threadIdx.x, lane = tid & 31, wid = tid >> 5;
    const int m0 = blockIdx.y * 128, n0 = blockIdx.x * 128;
    const int wm = (wid >> 1) * 32, wn = (wid & 1) * 64;

    const __nv_bfloat16* tsrc[4] = {
        Ah + (size_t)m0 * HID, Al + (size_t)m0 * HID,
        Bh + (size_t)n0 * HID, Bl + (size_t)n0 * HID};

    float d[16][4];
#pragma unroll
    for (int i = 0; i < 16; ++i) { d[i][0] = d[i][1] = d[i][2] = d[i][3] = 0.f; }

    const int grp = lane >> 3, lr = lane & 7;
    const int arow_b = wm + (grp & 1) * 8 + lr;
    const int brow_b = wn + (grp >> 1) * 8 + lr;
    const int akc_b = grp >> 1;
    const int bkc_b = grp & 1;

    // prologue: stages 0, 1
#pragma unroll
    for (int pc = 0; pc < 2; ++pc) {
        int k0 = pc * 64;
        uint32_t sbase = sb + pc * 65536;
#pragma unroll
        for (int j = 0; j < 4; ++j) {
            int id = tid + j * 256;
            int r = id >> 3, c = id & 7;
            uint32_t doff = (uint32_t)(r * 128 + ((c ^ (r & 7)) << 4));
#pragma unroll
            for (int t = 0; t < 4; ++t)
                CP16(sbase + t * 16384 + doff, tsrc[t] + (size_t)r * HID + k0 + c * 8);
        }
        CP_COMMIT();
    }

    int sComp = 0, sPref = 2;
    for (int kc = 0; kc < 32; ++kc) {
        if (kc == 31) { CP_WAIT0(); } else { CP_WAIT1(); }
        __syncthreads();
        if (kc + 2 < 32) {
            int k0 = (kc + 2) * 64;
            uint32_t sbase = sb + sPref * 65536;
#pragma unroll
            for (int j = 0; j < 4; ++j) {
                int id = tid + j * 256;
                int r = id >> 3, c = id & 7;
                uint32_t doff = (uint32_t)(r * 128 + ((c ^ (r & 7)) << 4));
#pragma unroll
                for (int t = 0; t < 4; ++t)
                    CP16(sbase + t * 16384 + doff, tsrc[t] + (size_t)r * HID + k0 + c * 8);
            }
            CP_COMMIT();
            if (++sPref == 3) sPref = 0;
        }

        const uint32_t base = sb + sComp * 65536;
        if (++sComp == 3) sComp = 0;
        const uint32_t TAh = base, TAl = base + 16384, TBh = base + 32768, TBl = base + 49152;

#pragma unroll
        for (int ks = 0; ks < 4; ++ks) {
            uint32_t aH[2][4], aL[2][4], bH[4][4], bL[4][4];
#pragma unroll
            for (int f = 0; f < 2; ++f) {
                int row = arow_b + f * 16;
                int kc8 = ks * 2 + akc_b;
                uint32_t off = (uint32_t)(row * 128 + ((kc8 ^ (row & 7)) << 4));
                ldsm4(TAh + off, aH[f]);
                ldsm4(TAl + off, aL[f]);
            }
#pragma unroll
            for (int jn = 0; jn < 4; ++jn) {
                int row = brow_b + jn * 16;
                int kc8 = ks * 2 + bkc_b;
                uint32_t off = (uint32_t)(row * 128 + ((kc8 ^ (row & 7)) << 4));
                ldsm4(TBh + off, bH[jn]);
                ldsm4(TBl + off, bL[jn]);
            }
#pragma unroll
            for (int f = 0; f < 2; ++f) {
#pragma unroll
                for (int jn = 0; jn < 4; ++jn) {
#pragma unroll
                    for (int sub = 0; sub < 2; ++sub) {
                        float* dd = d[f * 8 + jn * 2 + sub];
                        uint32_t h0 = bH[jn][sub * 2], h1 = bH[jn][sub * 2 + 1];
                        mma16816(dd, aH[f], h0, h1);
                        mma16816(dd, aH[f], bL[jn][sub * 2], bL[jn][sub * 2 + 1]);
                        mma16816(dd, aL[f], h0, h1);
                    }
                }
            }
        }
    }

    // epilogue
    const int rq = lane >> 2, cq = (lane & 3) * 2;
#pragma unroll
    for (int j = 0; j < 8; ++j) {
        int col = n0 + wn + j * 8 + cq;
        float2 bb = *(const float2*)&bias[col];
#pragma unroll
        for (int f = 0; f < 2; ++f) {
            const float* dd = d[f * 8 + j];
            int row = m0 + wm + f * 16 + rq;
            float2 o0 = {dd[0] + bb.x, dd[1] + bb.y};
            float2 o1 = {dd[2] + bb.x, dd[3] + bb.y};
            *(float2*)&C[(size_t)row * HID + col]       = o0;
            *(float2*)&C[(size_t)(row + 8) * HID + col] = o1;
            if (Ch) {
                split_store(Ch, Cl, row, col, o0);
                split_store(Ch, Cl, row + 8, col, o1);
            }
        }
    }
}

// ---------------- column sum of Q (for qbar) ----------------
__global__ void colsum_part() {
    int c = blockIdx.x * 256 + threadIdx.x;
    int chunk = blockIdx.y;
    int n0 = chunk * 128;
    float s = 0.f;
#pragma unroll 8
    for (int n = 0; n < 128; ++n) s += g_Q[(n0 + n) * HID + c];
    g_part[chunk * HID + c] = s;
}

__global__ void colsum_final() {
    int c = blockIdx.x * 256 + threadIdx.x;
    float s = 0.f;
#pragma unroll
    for (int t = 0; t < 16; ++t) s += g_part[t * HID + c];
    g_qbar[c] = s;
}

// ---------------- importance[h, m] = qbar_h . k_m ----------------
__global__ void imp_kernel() {
    int gw = (blockIdx.x * blockDim.x + threadIdx.x) >> 5;
    int lane = threadIdx.x & 31;
    int h = gw >> 11, m = gw & 2047;
    float4 kv = *(const float4*)&g_K[(size_t)m * HID + h * HD + lane * 4];
    float4 qv = *(const float4*)&g_qbar[h * HD + lane * 4];
    float s = kv.x * qv.x + kv.y * qv.y + kv.z * qv.z + kv.w * qv.w;
#pragma unroll
    for (int o = 16; o; o >>= 1) s += __shfl_xor_sync(0xffffffffu, s, o);
    if (!lane) g_imp[h * NSEQ + m] = s;
}

// ---------------- top-k by rank counting ----------------
__global__ void topk_kernel() {
    __shared__ float sv[NSEQ];
    __shared__ int scnt;
    int h = blockIdx.x, tid = threadIdx.x;
    if (tid == 0) scnt = 0;
    for (int i = tid; i < NSEQ; i += 256) sv[i] = g_imp[h * NSEQ + i];
    __syncthreads();
    const float4* p4 = (const float4*)sv;
#pragma unroll
    for (int e = 0; e < 8; ++e) {
        int m = e * 256 + tid;
        float v = sv[m];
        int rank = 0;
        for (int j4 = 0; j4 < NSEQ / 4; ++j4) {
            float4 x = p4[j4];
            int jb = j4 * 4;
            rank += (x.x > v) + (x.y > v) + (x.z > v) + (x.w > v);
            rank += (x.x == v && jb + 0 < m);
            rank += (x.y == v && jb + 1 < m);
            rank += (x.z == v && jb + 2 < m);
            rank += (x.w == v && jb + 3 < m);
        }
        if (rank < TOPK) {
            int pos = atomicAdd(&scnt, 1);
            g_idx[h * TOPK + pos] = m;
        }
    }
}

// ======================= HMMA bf16x3 sparse attention =======================
// block = (64-query tile, head), 256 threads / 8 warps.
// smem bytes: QH 0..16K | QL 16K..32K | K/V stages 32K..96K (2 x (h16K + l16K))
//             S 96K..160K (64 rows x 1024B; after softmax row r holds Wh[512] Wl[512])
//             sidx 160K..161K
#define AT_QH   0
#define AT_QL   16384
#define AT_KST  32768
#define AT_S    98304
#define AT_IDX  163840
#define ATTN_SMEM (163840 + 1024)

__device__ __forceinline__ void gather_kv(uint32_t dstStage,
                                          const __nv_bfloat16* __restrict__ Hi,
                                          const __nv_bfloat16* __restrict__ Lo,
                                          const int* sidx, int kc, int tid, int HB) {
#pragma unroll
    for (int j = 0; j < 4; ++j) {
        int id = tid + j * 256;
        int r = id >> 4, c = id & 15;
        int key = sidx[kc * 64 + r];
        uint32_t dst = dstStage + (uint32_t)(r * 256 + ((c ^ (r & 7)) << 4));
        CP16(dst,         Hi + (size_t)key * HID + HB + c * 8);
        CP16(dst + 16384, Lo + (size_t)key * HID + HB + c * 8);
    }
}

__global__ __launch_bounds__(256, 1)
void attn_mma() {
    extern __shared__ char smc[];
    const uint32_t sb = (uint32_t)__cvta_generic_to_shared(smc);
    const int tid = threadIdx.x, lane = tid & 31, wid = tid >> 5;
    const int h = blockIdx.y, n0 = blockIdx.x * 64, HB = h * HD;
    const int grp = lane >> 3, lr = lane & 7;
    const int fm = wid >> 1;                 // 0..3 (m group of 16 rows)
    const int rq = lane >> 2, cq = (lane & 3) * 2;
    const float SCALE = 0.08838834764831845f;

    int* sidx = (int*)(smc + AT_IDX);
    sidx[tid] = g_idx[h * TOPK + tid];
    __syncthreads();

    // prologue: Q tiles + K chunk 0
#pragma unroll
    for (int j = 0; j < 4; ++j) {
        int id = tid + j * 256;
        int r = id >> 4, c = id & 15;
        uint32_t dst = sb + AT_QH + (uint32_t)(r * 256 + ((c ^ (r & 7)) << 4));
        CP16(dst,         g_Qh + (size_t)(n0 + r) * HID + HB + c * 8);
        CP16(dst + 16384, g_Ql + (size_t)(n0 + r) * HID + HB + c * 8);
    }
    gather_kv(sb + AT_KST, g_Kh, g_Kl, sidx, 0, tid, HB);
    CP_COMMIT();

    // ---- phase 1: S = scale * (QhKh + QhKl + QlKh)^T over 4 key chunks ----
    const int wn1 = (wid & 1) * 32;          // key offset within chunk
    float* Sf = (float*)(smc + AT_S);
    for (int kc = 0; kc < 4; ++kc) {
        CP_WAIT0();
        __syncthreads();
        if (kc + 1 < 4) {
            gather_kv(sb + AT_KST + ((kc + 1) & 1) * 32768, g_Kh, g_Kl, sidx, kc + 1, tid, HB);
            CP_COMMIT();
        }
        const uint32_t KH = sb + AT_KST + (kc & 1) * 32768, KL = KH + 16384;
        const uint32_t QH = sb + AT_QH, QL = sb + AT_QL;
        float acc[4][4] = {};
        const int arow = fm * 16 + (grp & 1) * 8 + lr;
        const int brow = wn1 + (grp >> 1) * 8 + lr;
#pragma unroll
        for (int ks = 0; ks < 8; ++ks) {
            uint32_t aH[4], aL[4], bH[2][4], bL[2][4];
            {
                int ca = ks * 2 + (grp >> 1);
                uint32_t off = (uint32_t)(arow * 256 + ((ca ^ (arow & 7)) << 4));
                ldsm4(QH + off, aH);
                ldsm4(QL + off, aL);
            }
            {
                int cb = ks * 2 + (grp & 1);
#pragma unroll
                for (int hf = 0; hf < 2; ++hf) {
                    int row = brow + hf * 16;
                    uint32_t off = (uint32_t)(row * 256 + ((cb ^ (row & 7)) << 4));
                    ldsm4(KH + off, bH[hf]);
                    ldsm4(KL + off, bL[hf]);
                }
            }
#pragma unroll
            for (int hf = 0; hf < 2; ++hf)
#pragma unroll
                for (int sub = 0; sub < 2; ++sub) {
                    float* dd = acc[hf * 2 + sub];
                    uint32_t h0 = bH[hf][sub * 2], h1 = bH[hf][sub * 2 + 1];
                    mma16816(dd, aH, h0, h1);
                    mma16816(dd, aH, bL[hf][sub * 2], bL[hf][sub * 2 + 1]);
                    mma16816(dd, aL, h0, h1);
                }
        }
#pragma unroll
        for (int jf = 0; jf < 4; ++jf) {
            int col = kc * 64 + wn1 + jf * 8 + cq;
            float2 v0 = {acc[jf][0] * SCALE, acc[jf][1] * SCALE};
            float2 v1 = {acc[jf][2] * SCALE, acc[jf][3] * SCALE};
            *(float2*)&Sf[(fm * 16 + rq) * 256 + col]     = v0;
            *(float2*)&Sf[(fm * 16 + rq + 8) * 256 + col] = v1;
        }
    }
    __syncthreads();

    // prefetch V chunk 0 (stage 0; K data no longer needed), overlap with softmax
    gather_kv(sb + AT_KST, g_Vh, g_Vl, sidx, 0, tid, HB);
    CP_COMMIT();

    // ---- phase 2: softmax, pack weights into Wh/Wl (row-local, in place over S) ----
    {
        for (int r = wid; r < 64; r += 8) {
            float vals[8], mx = -1e30f;
            float* Sr = (float*)(smc + AT_S + r * 1024);
#pragma unroll
            for (int t = 0; t < 8; ++t) {
                vals[t] = Sr[lane + t * 32];
                mx = fmaxf(mx, vals[t]);
            }
#pragma unroll
            for (int o = 16; o; o >>= 1) mx = fmaxf(mx, __shfl_xor_sync(0xffffffffu, mx, o));
            float ssum = 0.f;
#pragma unroll
            for (int t = 0; t < 8; ++t) { vals[t] = expf(vals[t] - mx); ssum += vals[t]; }
#pragma unroll
            for (int o = 16; o; o >>= 1) ssum += __shfl_xor_sync(0xffffffffu, ssum, o);
            float inv = 1.0f / ssum;
            char* rowb = smc + AT_S + r * 1024;
#pragma unroll
            for (int t = 0; t < 8; ++t) {
                float w = vals[t] * inv;
                __nv_bfloat16 hi = __float2bfloat16(w);
                __nv_bfloat16 lo = __float2bfloat16(w - __bfloat162float(hi));
                int key = lane + t * 32;
                int c = key >> 3, wi = key & 7;
                int swz = ((c ^ (r & 7)) << 4) + wi * 2;
                *(__nv_bfloat16*)(rowb + swz)       = hi;
                *(__nv_bfloat16*)(rowb + 512 + swz) = lo;
            }
        }
    }

    // ---- phase 3: O = (WhVh + WhVl + WlVh) over 4 key chunks ----
    float oacc[8][4];
#pragma unroll
    for (int i = 0; i < 8; ++i) { oacc[i][0] = oacc[i][1] = oacc[i][2] = oacc[i][3] = 0.f; }
    const int wn3 = (wid & 1) * 64;          // dim offset
    for (int kc = 0; kc < 4; ++kc) {
        CP_WAIT0();
        __syncthreads();
        if (kc + 1 < 4) {
            gather_kv(sb + AT_KST + ((kc + 1) & 1) * 32768, g_Vh, g_Vl, sidx, kc + 1, tid, HB);
            CP_COMMIT();
        }
        const uint32_t VH = sb + AT_KST + (kc & 1) * 32768, VL = VH + 16384;
#pragma unroll
        for (int ks = 0; ks < 4; ++ks) {     // 16 keys per step
            uint32_t aH[4], aL[4];
            {
                int cg = kc * 8 + ks * 2 + (grp >> 1);
                int arow = fm * 16 + (grp & 1) * 8 + lr;
                uint32_t off = (uint32_t)(arow * 1024 + ((cg ^ (arow & 7)) << 4));
                ldsm4(sb + AT_S + off, aH);
                ldsm4(sb + AT_S + off + 512, aL);
            }
            uint32_t bH[4][4], bL[4][4];
            {
                int vrow = ks * 16 + (grp & 1) * 8 + lr;
                uint32_t rbase = (uint32_t)(vrow * 256);
                int cbase = (wn3 >> 3) + (grp >> 1);
#pragma unroll
                for (int g4 = 0; g4 < 4; ++g4) {
                    int cn = cbase + g4 * 2;
                    uint32_t off = rbase + ((cn ^ (vrow & 7)) << 4);
                    ldsm4t(VH + off, bH[g4]);
                    ldsm4t(VL + off, bL[g4]);
                }
            }
#pragma unroll
            for (int g4 = 0; g4 < 4; ++g4)
#pragma unroll
                for (int s2 = 0; s2 < 2; ++s2) {
                    float* dd = oacc[g4 * 2 + s2];
                    uint32_t h0 = bH[g4][s2 * 2], h1 = bH[g4][s2 * 2 + 1];
                    mma16816(dd, aH, h0, h1);
                    mma16816(dd, aH, bL[g4][s2 * 2], bL[g4][s2 * 2 + 1]);
                    mma16816(dd, aL, h0, h1);
                }
        }
    }

    // epilogue: split O into Oh/Ol directly
#pragma unroll
    for (int j = 0; j < 8; ++j) {
        int col = HB + wn3 + j * 8 + cq;
        int row = n0 + fm * 16 + rq;
        float2 v0 = {oacc[j][0], oacc[j][1]};
        float2 v1 = {oacc[j][2], oacc[j][3]};
        split_store(g_Oh, g_Ol, row, col, v0);
        split_store(g_Oh, g_Ol, row + 8, col, v1);
    }
}

// ======================= host =======================
extern "C" void kernel_launch(void* const* d_in, const int* in_sizes, int n_in,
                              void* d_out, int out_size) {
    const float* X  = (const float*)d_in[0];
    const float* Wq = (const float*)d_in[1];
    const float* bq = (const float*)d_in[2];
    const float* Wk = (const float*)d_in[3];
    const float* bk = (const float*)d_in[4];
    const float* Wv = (const float*)d_in[5];
    const float* bv = (const float*)d_in[6];
    const float* Wo = (const float*)d_in[7];
    const float* bo = (const float*)d_in[8];
    float* out = (float*)d_out;

    float *Qd, *Kd, *Vd;
    __nv_bfloat16 *Xh, *Xl, *Oh, *Ol, *Wh, *Wl, *Qh, *Ql, *Kh, *Kl, *Vh, *Vl;
    cudaGetSymbolAddress((void**)&Qd, g_Q);
    cudaGetSymbolAddress((void**)&Kd, g_K);
    cudaGetSymbolAddress((void**)&Vd, g_V);
    cudaGetSymbolAddress((void**)&Xh, g_Xh);
    cudaGetSymbolAddress((void**)&Xl, g_Xl);
    cudaGetSymbolAddress((void**)&Oh, g_Oh);
    cudaGetSymbolAddress((void**)&Ol, g_Ol);
    cudaGetSymbolAddress((void**)&Wh, g_Wh);
    cudaGetSymbolAddress((void**)&Wl, g_Wl);
    cudaGetSymbolAddress((void**)&Qh, g_Qh);
    cudaGetSymbolAddress((void**)&Ql, g_Ql);
    cudaGetSymbolAddress((void**)&Kh, g_Kh);
    cudaGetSymbolAddress((void**)&Kl, g_Kl);
    cudaGetSymbolAddress((void**)&Vh, g_Vh);
    cudaGetSymbolAddress((void**)&Vl, g_Vl);

    cudaFuncSetAttribute(gemm_bf16x3, cudaFuncAttributeMaxDynamicSharedMemorySize, GSMEM);
    cudaFuncSetAttribute(attn_mma, cudaFuncAttributeMaxDynamicSharedMemorySize, ATTN_SMEM);

    const size_t WSZ = (size_t)HID * HID;

    split_f32<<<4096, 256>>>(X, Xh, Xl);
    transpose_split4<<<dim3(64, 64, 4), dim3(32, 8)>>>(Wq, Wk, Wv, Wo);

    dim3 gg(16, 16);
    gemm_bf16x3<<<gg, 256, GSMEM>>>(Xh, Xl, Wh + 0 * WSZ, Wl + 0 * WSZ, bq, Qd, Qh, Ql);
    gemm_bf16x3<<<gg, 256, GSMEM>>>(Xh, Xl, Wh + 1 * WSZ, Wl + 1 * WSZ, bk, Kd, Kh, Kl);
    gemm_bf16x3<<<gg, 256, GSMEM>>>(Xh, Xl, Wh + 2 * WSZ, Wl + 2 * WSZ, bv, Vd, Vh, Vl);

    colsum_part<<<dim3(8, 16), 256>>>();
    colsum_final<<<8, 256>>>();
    imp_kernel<<<4096, 256>>>();
    topk_kernel<<<16, 256>>>();

    attn_mma<<<dim3(32, 16), 256, ATTN_SMEM>>>();

    gemm_bf16x3<<<gg, 256, GSMEM>>>(Oh, Ol, Wh + 3 * WSZ, Wl + 3 * WSZ, bo, out,
                                    nullptr, nullptr);
}

// round 7
// speedup vs baseline: 3.1124x; 1.1819x over previous
#include <cuda_runtime.h>
#include <cuda_bf16.h>
#include <math.h>
#include <stdint.h>

#define HID  2048
#define NSEQ 2048
#define NH   16
#define HD   128
#define TOPK 256

// ---------------- scratch (device globals; no allocation) ----------------
__device__ float g_Q[NSEQ * HID];
__device__ float g_K[NSEQ * HID];
__device__ float g_part[16 * HID];
__device__ float g_qbar[HID];
__device__ float g_imp[NH * NSEQ];
__device__ int   g_idx[NH * TOPK];
__device__ int   g_cnt[NH];

__device__ __align__(16) __nv_bfloat16 g_Xh[NSEQ * HID];
__device__ __align__(16) __nv_bfloat16 g_Xl[NSEQ * HID];
__device__ __align__(16) __nv_bfloat16 g_Oh[NSEQ * HID];
__device__ __align__(16) __nv_bfloat16 g_Ol[NSEQ * HID];
__device__ __align__(16) __nv_bfloat16 g_Qh[NSEQ * HID];
__device__ __align__(16) __nv_bfloat16 g_Ql[NSEQ * HID];
__device__ __align__(16) __nv_bfloat16 g_Kh[NSEQ * HID];
__device__ __align__(16) __nv_bfloat16 g_Kl[NSEQ * HID];
__device__ __align__(16) __nv_bfloat16 g_Vh[NSEQ * HID];
__device__ __align__(16) __nv_bfloat16 g_Vl[NSEQ * HID];
__device__ __align__(16) __nv_bfloat16 g_Wh[4][HID * HID];   // W^T splits, [N][K]
__device__ __align__(16) __nv_bfloat16 g_Wl[4][HID * HID];

// ======================= PTX helpers (plain sm_103-safe) =======================
__device__ __forceinline__ void ldsm4(uint32_t addr, uint32_t* r) {
    asm volatile("ldmatrix.sync.aligned.m8n8.x4.shared.b16 {%0,%1,%2,%3}, [%4];"
                 : "=r"(r[0]), "=r"(r[1]), "=r"(r[2]), "=r"(r[3]) : "r"(addr));
}
__device__ __forceinline__ void ldsm4t(uint32_t addr, uint32_t* r) {
    asm volatile("ldmatrix.sync.aligned.m8n8.x4.trans.shared.b16 {%0,%1,%2,%3}, [%4];"
                 : "=r"(r[0]), "=r"(r[1]), "=r"(r[2]), "=r"(r[3]) : "r"(addr));
}
__device__ __forceinline__ void mma16816(float* d, const uint32_t* a, uint32_t b0, uint32_t b1) {
    asm volatile("mma.sync.aligned.m16n8k16.row.col.f32.bf16.bf16.f32 "
                 "{%0,%1,%2,%3}, {%4,%5,%6,%7}, {%8,%9}, {%0,%1,%2,%3};"
                 : "+f"(d[0]), "+f"(d[1]), "+f"(d[2]), "+f"(d[3])
                 : "r"(a[0]), "r"(a[1]), "r"(a[2]), "r"(a[3]), "r"(b0), "r"(b1));
}
#define CP16(dst, src) \
    asm volatile("cp.async.cg.shared.global [%0], [%1], 16;" :: "r"(dst), "l"(src))
#define CP_COMMIT() asm volatile("cp.async.commit_group;" ::: "memory")
#define CP_WAIT1()  asm volatile("cp.async.wait_group 1;" ::: "memory")
#define CP_WAIT0()  asm volatile("cp.async.wait_group 0;" ::: "memory")

__device__ __forceinline__ void split_store(__nv_bfloat16* Ch, __nv_bfloat16* Cl,
                                            int row, int col, float2 v) {
    __nv_bfloat16 h0 = __float2bfloat16(v.x), h1 = __float2bfloat16(v.y);
    uint32_t hw = (uint32_t)__bfloat16_as_ushort(h0) |
                  ((uint32_t)__bfloat16_as_ushort(h1) << 16);
    __nv_bfloat16 l0 = __float2bfloat16(v.x - __bfloat162float(h0));
    __nv_bfloat16 l1 = __float2bfloat16(v.y - __bfloat162float(h1));
    uint32_t lw = (uint32_t)__bfloat16_as_ushort(l0) |
                  ((uint32_t)__bfloat16_as_ushort(l1) << 16);
    *(uint32_t*)&Ch[(size_t)row * HID + col] = hw;
    *(uint32_t*)&Cl[(size_t)row * HID + col] = lw;
}

// ======================= split / transpose-split =======================
__global__ void split_f32(const float* __restrict__ x,
                          __nv_bfloat16* __restrict__ hi, __nv_bfloat16* __restrict__ lo) {
    int i = (blockIdx.x * 256 + threadIdx.x) * 4;
    float4 v = *(const float4*)(x + i);
    __nv_bfloat16 h0 = __float2bfloat16(v.x);
    __nv_bfloat16 h1 = __float2bfloat16(v.y);
    __nv_bfloat16 h2 = __float2bfloat16(v.z);
    __nv_bfloat16 h3 = __float2bfloat16(v.w);
    ushort4 hv = {__bfloat16_as_ushort(h0), __bfloat16_as_ushort(h1),
                  __bfloat16_as_ushort(h2), __bfloat16_as_ushort(h3)};
    __nv_bfloat16 l0 = __float2bfloat16(v.x - __bfloat162float(h0));
    __nv_bfloat16 l1 = __float2bfloat16(v.y - __bfloat162float(h1));
    __nv_bfloat16 l2 = __float2bfloat16(v.z - __bfloat162float(h2));
    __nv_bfloat16 l3 = __float2bfloat16(v.w - __bfloat162float(h3));
    ushort4 lv = {__bfloat16_as_ushort(l0), __bfloat16_as_ushort(l1),
                  __bfloat16_as_ushort(l2), __bfloat16_as_ushort(l3)};
    *(ushort4*)(hi + i) = hv;
    *(ushort4*)(lo + i) = lv;
}

// all 4 weights: [K][N] fp32 -> [N][K] bf16 hi/lo
__global__ void transpose_split4(const float* __restrict__ W0, const float* __restrict__ W1,
                                 const float* __restrict__ W2, const float* __restrict__ W3) {
    __shared__ float t[32][33];
    const float* W = blockIdx.z == 0 ? W0 : blockIdx.z == 1 ? W1 : blockIdx.z == 2 ? W2 : W3;
    __nv_bfloat16* Th = g_Wh[blockIdx.z];
    __nv_bfloat16* Tl = g_Wl[blockIdx.z];
    int n0 = blockIdx.x * 32, k0 = blockIdx.y * 32;
    int tx = threadIdx.x, ty = threadIdx.y;  // block (32, 8)
#pragma unroll
    for (int j = 0; j < 32; j += 8)
        t[ty + j][tx] = W[(size_t)(k0 + ty + j) * HID + n0 + tx];
    __syncthreads();
#pragma unroll
    for (int j = 0; j < 32; j += 8) {
        float v = t[tx][ty + j];
        __nv_bfloat16 h = __float2bfloat16(v);
        size_t o = (size_t)(n0 + ty + j) * HID + k0 + tx;
        Th[o] = h;
        Tl[o] = __float2bfloat16(v - __bfloat162float(h));
    }
}

// ======================= HMMA bf16x3 GEMM (3-stage pipeline) =======================
// C = (Ah+Al)[M,K] @ (Bh+Bl)^T ([N,K]) + bias. CTA 128x128, BK=64, 8 warps (32x64).
// Stage: Ah|Al|Bh|Bl (16KB each) = 64KB; 3 stages = 192KB.
#define GSMEM (3 * 65536)

__global__ __launch_bounds__(256, 1)
void gemm_bf16x3(const __nv_bfloat16* __restrict__ Ah, const __nv_bfloat16* __restrict__ Al,
                 const __nv_bfloat16* __restrict__ Bh, const __nv_bfloat16* __restrict__ Bl,
                 const float* __restrict__ bias, float* __restrict__ C,
                 __nv_bfloat16* __restrict__ Ch, __nv_bfloat16* __restrict__ Cl) {
    extern __shared__ char smem[];
    const uint32_t sb = (uint32_t)__cvta_generic_to_shared(smem);
    const int tid = threadIdx.x, lane = tid & 31, wid = tid >> 5;
    const int m0 = blockIdx.y * 128, n0 = blockIdx.x * 128;
    const int wm = (wid >> 1) * 32, wn = (wid & 1) * 64;

    const __nv_bfloat16* tsrc[4] = {
        Ah + (size_t)m0 * HID, Al + (size_t)m0 * HID,
        Bh + (size_t)n0 * HID, Bl + (size_t)n0 * HID};

    float d[16][4];
#pragma unroll
    for (int i = 0; i < 16; ++i) { d[i][0] = d[i][1] = d[i][2] = d[i][3] = 0.f; }

    const int grp = lane >> 3, lr = lane & 7;
    const int arow_b = wm + (grp & 1) * 8 + lr;
    const int brow_b = wn + (grp >> 1) * 8 + lr;
    const int akc_b = grp >> 1;
    const int bkc_b = grp & 1;

    // prologue: stages 0, 1
#pragma unroll
    for (int pc = 0; pc < 2; ++pc) {
        int k0 = pc * 64;
        uint32_t sbase = sb + pc * 65536;
#pragma unroll
        for (int j = 0; j < 4; ++j) {
            int id = tid + j * 256;
            int r = id >> 3, c = id & 7;
            uint32_t doff = (uint32_t)(r * 128 + ((c ^ (r & 7)) << 4));
#pragma unroll
            for (int t = 0; t < 4; ++t)
                CP16(sbase + t * 16384 + doff, tsrc[t] + (size_t)r * HID + k0 + c * 8);
        }
        CP_COMMIT();
    }

    int sComp = 0, sPref = 2;
    for (int kc = 0; kc < 32; ++kc) {
        if (kc == 31) { CP_WAIT0(); } else { CP_WAIT1(); }
        __syncthreads();
        if (kc + 2 < 32) {
            int k0 = (kc + 2) * 64;
            uint32_t sbase = sb + sPref * 65536;
#pragma unroll
            for (int j = 0; j < 4; ++j) {
                int id = tid + j * 256;
                int r = id >> 3, c = id & 7;
                uint32_t doff = (uint32_t)(r * 128 + ((c ^ (r & 7)) << 4));
#pragma unroll
                for (int t = 0; t < 4; ++t)
                    CP16(sbase + t * 16384 + doff, tsrc[t] + (size_t)r * HID + k0 + c * 8);
            }
            CP_COMMIT();
            if (++sPref == 3) sPref = 0;
        }

        const uint32_t base = sb + sComp * 65536;
        if (++sComp == 3) sComp = 0;
        const uint32_t TAh = base, TAl = base + 16384, TBh = base + 32768, TBl = base + 49152;

#pragma unroll
        for (int ks = 0; ks < 4; ++ks) {
            uint32_t aH[2][4], aL[2][4], bH[4][4], bL[4][4];
#pragma unroll
            for (int f = 0; f < 2; ++f) {
                int row = arow_b + f * 16;
                int kc8 = ks * 2 + akc_b;
                uint32_t off = (uint32_t)(row * 128 + ((kc8 ^ (row & 7)) << 4));
                ldsm4(TAh + off, aH[f]);
                ldsm4(TAl + off, aL[f]);
            }
#pragma unroll
            for (int jn = 0; jn < 4; ++jn) {
                int row = brow_b + jn * 16;
                int kc8 = ks * 2 + bkc_b;
                uint32_t off = (uint32_t)(row * 128 + ((kc8 ^ (row & 7)) << 4));
                ldsm4(TBh + off, bH[jn]);
                ldsm4(TBl + off, bL[jn]);
            }
            // product-major sweeps: 16 independent accumulators per sweep (no RAW chains)
#pragma unroll
            for (int f = 0; f < 2; ++f)
#pragma unroll
                for (int jn = 0; jn < 4; ++jn)
#pragma unroll
                    for (int sub = 0; sub < 2; ++sub)
                        mma16816(d[f * 8 + jn * 2 + sub], aH[f],
                                 bH[jn][sub * 2], bH[jn][sub * 2 + 1]);
#pragma unroll
            for (int f = 0; f < 2; ++f)
#pragma unroll
                for (int jn = 0; jn < 4; ++jn)
#pragma unroll
                    for (int sub = 0; sub < 2; ++sub)
                        mma16816(d[f * 8 + jn * 2 + sub], aH[f],
                                 bL[jn][sub * 2], bL[jn][sub * 2 + 1]);
#pragma unroll
            for (int f = 0; f < 2; ++f)
#pragma unroll
                for (int jn = 0; jn < 4; ++jn)
#pragma unroll
                    for (int sub = 0; sub < 2; ++sub)
                        mma16816(d[f * 8 + jn * 2 + sub], aL[f],
                                 bH[jn][sub * 2], bH[jn][sub * 2 + 1]);
        }
    }

    // epilogue
    const int rq = lane >> 2, cq = (lane & 3) * 2;
#pragma unroll
    for (int j = 0; j < 8; ++j) {
        int col = n0 + wn + j * 8 + cq;
        float2 bb = *(const float2*)&bias[col];
#pragma unroll
        for (int f = 0; f < 2; ++f) {
            const float* dd = d[f * 8 + j];
            int row = m0 + wm + f * 16 + rq;
            float2 o0 = {dd[0] + bb.x, dd[1] + bb.y};
            float2 o1 = {dd[2] + bb.x, dd[3] + bb.y};
            if (C) {
                *(float2*)&C[(size_t)row * HID + col]       = o0;
                *(float2*)&C[(size_t)(row + 8) * HID + col] = o1;
            }
            if (Ch) {
                split_store(Ch, Cl, row, col, o0);
                split_store(Ch, Cl, row + 8, col, o1);
            }
        }
    }
}

// ---------------- column sum of Q (for qbar) ----------------
__global__ void colsum_part() {
    int c = blockIdx.x * 256 + threadIdx.x;
    int chunk = blockIdx.y;
    int n0 = chunk * 128;
    float s = 0.f;
#pragma unroll 8
    for (int n = 0; n < 128; ++n) s += g_Q[(n0 + n) * HID + c];
    g_part[chunk * HID + c] = s;
}

__global__ void colsum_final() {
    int c = blockIdx.x * 256 + threadIdx.x;
    float s = 0.f;
#pragma unroll
    for (int t = 0; t < 16; ++t) s += g_part[t * HID + c];
    g_qbar[c] = s;
}

// ---------------- importance[h, m] = qbar_h . k_m ----------------
__global__ void imp_kernel() {
    if (blockIdx.x == 0 && threadIdx.x < NH) g_cnt[threadIdx.x] = 0;
    int gw = (blockIdx.x * blockDim.x + threadIdx.x) >> 5;
    int lane = threadIdx.x & 31;
    int h = gw >> 11, m = gw & 2047;
    float4 kv = *(const float4*)&g_K[(size_t)m * HID + h * HD + lane * 4];
    float4 qv = *(const float4*)&g_qbar[h * HD + lane * 4];
    float s = kv.x * qv.x + kv.y * qv.y + kv.z * qv.z + kv.w * qv.w;
#pragma unroll
    for (int o = 16; o; o >>= 1) s += __shfl_xor_sync(0xffffffffu, s, o);
    if (!lane) g_imp[h * NSEQ + m] = s;
}

// ---------------- top-k by rank counting (64 blocks: 4 segments/head) ----------------
__global__ void topk_kernel() {
    __shared__ float sv[NSEQ];
    int h = blockIdx.x >> 2, seg = blockIdx.x & 3, tid = threadIdx.x;
    for (int i = tid; i < NSEQ; i += 256) sv[i] = g_imp[h * NSEQ + i];
    __syncthreads();
    const float4* p4 = (const float4*)sv;
#pragma unroll
    for (int e = 0; e < 2; ++e) {
        int m = seg * 512 + e * 256 + tid;
        float v = sv[m];
        int rank = 0;
        for (int j4 = 0; j4 < NSEQ / 4; ++j4) {
            float4 x = p4[j4];
            int jb = j4 * 4;
            rank += (x.x > v) + (x.y > v) + (x.z > v) + (x.w > v);
            rank += (x.x == v && jb + 0 < m);
            rank += (x.y == v && jb + 1 < m);
            rank += (x.z == v && jb + 2 < m);
            rank += (x.w == v && jb + 3 < m);
        }
        if (rank < TOPK) {
            int pos = atomicAdd(&g_cnt[h], 1);
            g_idx[h * TOPK + pos] = m;
        }
    }
}

// ======================= HMMA bf16x3 sparse attention =======================
#define AT_QH   0
#define AT_QL   16384
#define AT_KST  32768
#define AT_S    98304
#define AT_IDX  163840
#define ATTN_SMEM (163840 + 1024)

__device__ __forceinline__ void gather_kv(uint32_t dstStage,
                                          const __nv_bfloat16* __restrict__ Hi,
                                          const __nv_bfloat16* __restrict__ Lo,
                                          const int* sidx, int kc, int tid, int HB) {
#pragma unroll
    for (int j = 0; j < 4; ++j) {
        int id = tid + j * 256;
        int r = id >> 4, c = id & 15;
        int key = sidx[kc * 64 + r];
        uint32_t dst = dstStage + (uint32_t)(r * 256 + ((c ^ (r & 7)) << 4));
        CP16(dst,         Hi + (size_t)key * HID + HB + c * 8);
        CP16(dst + 16384, Lo + (size_t)key * HID + HB + c * 8);
    }
}

__global__ __launch_bounds__(256, 1)
void attn_mma() {
    extern __shared__ char smc[];
    const uint32_t sb = (uint32_t)__cvta_generic_to_shared(smc);
    const int tid = threadIdx.x, lane = tid & 31, wid = tid >> 5;
    const int h = blockIdx.y, n0 = blockIdx.x * 64, HB = h * HD;
    const int grp = lane >> 3, lr = lane & 7;
    const int fm = wid >> 1;
    const int rq = lane >> 2, cq = (lane & 3) * 2;
    const float SCALE = 0.08838834764831845f;

    int* sidx = (int*)(smc + AT_IDX);
    sidx[tid] = g_idx[h * TOPK + tid];
    __syncthreads();

#pragma unroll
    for (int j = 0; j < 4; ++j) {
        int id = tid + j * 256;
        int r = id >> 4, c = id & 15;
        uint32_t dst = sb + AT_QH + (uint32_t)(r * 256 + ((c ^ (r & 7)) << 4));
        CP16(dst,         g_Qh + (size_t)(n0 + r) * HID + HB + c * 8);
        CP16(dst + 16384, g_Ql + (size_t)(n0 + r) * HID + HB + c * 8);
    }
    gather_kv(sb + AT_KST, g_Kh, g_Kl, sidx, 0, tid, HB);
    CP_COMMIT();

    // ---- phase 1: S = scale * (QhKh + QhKl + QlKh)^T over 4 key chunks ----
    const int wn1 = (wid & 1) * 32;
    float* Sf = (float*)(smc + AT_S);
    for (int kc = 0; kc < 4; ++kc) {
        CP_WAIT0();
        __syncthreads();
        if (kc + 1 < 4) {
            gather_kv(sb + AT_KST + ((kc + 1) & 1) * 32768, g_Kh, g_Kl, sidx, kc + 1, tid, HB);
            CP_COMMIT();
        }
        const uint32_t KH = sb + AT_KST + (kc & 1) * 32768, KL = KH + 16384;
        const uint32_t QH = sb + AT_QH, QL = sb + AT_QL;
        float acc[4][4] = {};
        const int arow = fm * 16 + (grp & 1) * 8 + lr;
        const int brow = wn1 + (grp >> 1) * 8 + lr;
#pragma unroll
        for (int ks = 0; ks < 8; ++ks) {
            uint32_t aH[4], aL[4], bH[2][4], bL[2][4];
            {
                int ca = ks * 2 + (grp >> 1);
                uint32_t off = (uint32_t)(arow * 256 + ((ca ^ (arow & 7)) << 4));
                ldsm4(QH + off, aH);
                ldsm4(QL + off, aL);
            }
            {
                int cb = ks * 2 + (grp & 1);
#pragma unroll
                for (int hf = 0; hf < 2; ++hf) {
                    int row = brow + hf * 16;
                    uint32_t off = (uint32_t)(row * 256 + ((cb ^ (row & 7)) << 4));
                    ldsm4(KH + off, bH[hf]);
                    ldsm4(KL + off, bL[hf]);
                }
            }
            // product-major sweeps
#pragma unroll
            for (int hf = 0; hf < 2; ++hf)
#pragma unroll
                for (int sub = 0; sub < 2; ++sub)
                    mma16816(acc[hf * 2 + sub], aH, bH[hf][sub * 2], bH[hf][sub * 2 + 1]);
#pragma unroll
            for (int hf = 0; hf < 2; ++hf)
#pragma unroll
                for (int sub = 0; sub < 2; ++sub)
                    mma16816(acc[hf * 2 + sub], aH, bL[hf][sub * 2], bL[hf][sub * 2 + 1]);
#pragma unroll
            for (int hf = 0; hf < 2; ++hf)
#pragma unroll
                for (int sub = 0; sub < 2; ++sub)
                    mma16816(acc[hf * 2 + sub], aL, bH[hf][sub * 2], bH[hf][sub * 2 + 1]);
        }
#pragma unroll
        for (int jf = 0; jf < 4; ++jf) {
            int col = kc * 64 + wn1 + jf * 8 + cq;
            float2 v0 = {acc[jf][0] * SCALE, acc[jf][1] * SCALE};
            float2 v1 = {acc[jf][2] * SCALE, acc[jf][3] * SCALE};
            *(float2*)&Sf[(fm * 16 + rq) * 256 + col]     = v0;
            *(float2*)&Sf[(fm * 16 + rq + 8) * 256 + col] = v1;
        }
    }
    __syncthreads();

    gather_kv(sb + AT_KST, g_Vh, g_Vl, sidx, 0, tid, HB);
    CP_COMMIT();

    // ---- phase 2: softmax, pack weights into Wh/Wl ----
    {
        for (int r = wid; r < 64; r += 8) {
            float vals[8], mx = -1e30f;
            float* Sr = (float*)(smc + AT_S + r * 1024);
#pragma unroll
            for (int t = 0; t < 8; ++t) {
                vals[t] = Sr[lane + t * 32];
                mx = fmaxf(mx, vals[t]);
            }
#pragma unroll
            for (int o = 16; o; o >>= 1) mx = fmaxf(mx, __shfl_xor_sync(0xffffffffu, mx, o));
            float ssum = 0.f;
#pragma unroll
            for (int t = 0; t < 8; ++t) { vals[t] = expf(vals[t] - mx); ssum += vals[t]; }
#pragma unroll
            for (int o = 16; o; o >>= 1) ssum += __shfl_xor_sync(0xffffffffu, ssum, o);
            float inv = 1.0f / ssum;
            char* rowb = smc + AT_S + r * 1024;
#pragma unroll
            for (int t = 0; t < 8; ++t) {
                float w = vals[t] * inv;
                __nv_bfloat16 hi = __float2bfloat16(w);
                __nv_bfloat16 lo = __float2bfloat16(w - __bfloat162float(hi));
                int key = lane + t * 32;
                int c = key >> 3, wi = key & 7;
                int swz = ((c ^ (r & 7)) << 4) + wi * 2;
                *(__nv_bfloat16*)(rowb + swz)       = hi;
                *(__nv_bfloat16*)(rowb + 512 + swz) = lo;
            }
        }
    }

    // ---- phase 3: O = (WhVh + WhVl + WlVh) over 4 key chunks ----
    float oacc[8][4];
#pragma unroll
    for (int i = 0; i < 8; ++i) { oacc[i][0] = oacc[i][1] = oacc[i][2] = oacc[i][3] = 0.f; }
    const int wn3 = (wid & 1) * 64;
    for (int kc = 0; kc < 4; ++kc) {
        CP_WAIT0();
        __syncthreads();
        if (kc + 1 < 4) {
            gather_kv(sb + AT_KST + ((kc + 1) & 1) * 32768, g_Vh, g_Vl, sidx, kc + 1, tid, HB);
            CP_COMMIT();
        }
        const uint32_t VH = sb + AT_KST + (kc & 1) * 32768, VL = VH + 16384;
#pragma unroll
        for (int ks = 0; ks < 4; ++ks) {
            uint32_t aH[4], aL[4];
            {
                int cg = kc * 8 + ks * 2 + (grp >> 1);
                int arow = fm * 16 + (grp & 1) * 8 + lr;
                uint32_t off = (uint32_t)(arow * 1024 + ((cg ^ (arow & 7)) << 4));
                ldsm4(sb + AT_S + off, aH);
                ldsm4(sb + AT_S + off + 512, aL);
            }
            uint32_t bH[4][4], bL[4][4];
            {
                int vrow = ks * 16 + (grp & 1) * 8 + lr;
                uint32_t rbase = (uint32_t)(vrow * 256);
                int cbase = (wn3 >> 3) + (grp >> 1);
#pragma unroll
                for (int g4 = 0; g4 < 4; ++g4) {
                    int cn = cbase + g4 * 2;
                    uint32_t off = rbase + ((cn ^ (vrow & 7)) << 4);
                    ldsm4t(VH + off, bH[g4]);
                    ldsm4t(VL + off, bL[g4]);
                }
            }
            // product-major sweeps
#pragma unroll
            for (int g4 = 0; g4 < 4; ++g4)
#pragma unroll
                for (int s2 = 0; s2 < 2; ++s2)
                    mma16816(oacc[g4 * 2 + s2], aH, bH[g4][s2 * 2], bH[g4][s2 * 2 + 1]);
#pragma unroll
            for (int g4 = 0; g4 < 4; ++g4)
#pragma unroll
                for (int s2 = 0; s2 < 2; ++s2)
                    mma16816(oacc[g4 * 2 + s2], aH, bL[g4][s2 * 2], bL[g4][s2 * 2 + 1]);
#pragma unroll
            for (int g4 = 0; g4 < 4; ++g4)
#pragma unroll
                for (int s2 = 0; s2 < 2; ++s2)
                    mma16816(oacc[g4 * 2 + s2], aL, bH[g4][s2 * 2], bH[g4][s2 * 2 + 1]);
        }
    }

    // epilogue: split O into Oh/Ol directly
#pragma unroll
    for (int j = 0; j < 8; ++j) {
        int col = HB + wn3 + j * 8 + cq;
        int row = n0 + fm * 16 + rq;
        float2 v0 = {oacc[j][0], oacc[j][1]};
        float2 v1 = {oacc[j][2], oacc[j][3]};
        split_store(g_Oh, g_Ol, row, col, v0);
        split_store(g_Oh, g_Ol, row + 8, col, v1);
    }
}

// ======================= host =======================
extern "C" void kernel_launch(void* const* d_in, const int* in_sizes, int n_in,
                              void* d_out, int out_size) {
    const float* X  = (const float*)d_in[0];
    const float* Wq = (const float*)d_in[1];
    const float* bq = (const float*)d_in[2];
    const float* Wk = (const float*)d_in[3];
    const float* bk = (const float*)d_in[4];
    const float* Wv = (const float*)d_in[5];
    const float* bv = (const float*)d_in[6];
    const float* Wo = (const float*)d_in[7];
    const float* bo = (const float*)d_in[8];
    float* out = (float*)d_out;

    float *Qd, *Kd;
    __nv_bfloat16 *Xh, *Xl, *Oh, *Ol, *Wh, *Wl, *Qh, *Ql, *Kh, *Kl, *Vh, *Vl;
    cudaGetSymbolAddress((void**)&Qd, g_Q);
    cudaGetSymbolAddress((void**)&Kd, g_K);
    cudaGetSymbolAddress((void**)&Xh, g_Xh);
    cudaGetSymbolAddress((void**)&Xl, g_Xl);
    cudaGetSymbolAddress((void**)&Oh, g_Oh);
    cudaGetSymbolAddress((void**)&Ol, g_Ol);
    cudaGetSymbolAddress((void**)&Wh, g_Wh);
    cudaGetSymbolAddress((void**)&Wl, g_Wl);
    cudaGetSymbolAddress((void**)&Qh, g_Qh);
    cudaGetSymbolAddress((void**)&Ql, g_Ql);
    cudaGetSymbolAddress((void**)&Kh, g_Kh);
    cudaGetSymbolAddress((void**)&Kl, g_Kl);
    cudaGetSymbolAddress((void**)&Vh, g_Vh);
    cudaGetSymbolAddress((void**)&Vl, g_Vl);

    cudaFuncSetAttribute(gemm_bf16x3, cudaFuncAttributeMaxDynamicSharedMemorySize, GSMEM);
    cudaFuncSetAttribute(attn_mma, cudaFuncAttributeMaxDynamicSharedMemorySize, ATTN_SMEM);

    const size_t WSZ = (size_t)HID * HID;

    split_f32<<<4096, 256>>>(X, Xh, Xl);
    transpose_split4<<<dim3(64, 64, 4), dim3(32, 8)>>>(Wq, Wk, Wv, Wo);

    dim3 gg(16, 16);
    gemm_bf16x3<<<gg, 256, GSMEM>>>(Xh, Xl, Wh + 0 * WSZ, Wl + 0 * WSZ, bq, Qd, Qh, Ql);
    gemm_bf16x3<<<gg, 256, GSMEM>>>(Xh, Xl, Wh + 1 * WSZ, Wl + 1 * WSZ, bk, Kd, Kh, Kl);
    gemm_bf16x3<<<gg, 256, GSMEM>>>(Xh, Xl, Wh + 2 * WSZ, Wl + 2 * WSZ, bv, nullptr, Vh, Vl);

    colsum_part<<<dim3(8, 16), 256>>>();
    colsum_final<<<8, 256>>>();
    imp_kernel<<<4096, 256>>>();
    topk_kernel<<<64, 256>>>();

    attn_mma<<<dim3(32, 16), 256, ATTN_SMEM>>>();

    gemm_bf16x3<<<gg, 256, GSMEM>>>(Oh, Ol, Wh + 3 * WSZ, Wl + 3 * WSZ, bo, out,
                                    nullptr, nullptr);
}